// round 15
// baseline (speedup 1.0000x reference)
#include <cuda_runtime.h>
#include <cstdint>

#define NN 10000
#define EE 100000
#define DD 768
#define HH 4
#define CC 192
#define LL 3
#define EDIMF 16
#define NRELC 10

// GEMM tiling: block 128x128, 8 warps as 2(m) x 4(n), warp tile 64x32
#define BM 128
#define BN 128
#define BK 32
#define NKT (DD / BK)
#define GSTAGES 3
#define SA 36
#define SB 136
#define AS_FLOATS (BM * SA)
#define BS_FLOATS (BK * SB)
#define STAGE_FLOATS (AS_FLOATS + BS_FLOATS)
#define GEMM_SMEM (GSTAGES * STAGE_FLOATS * 4)   // ~105 KB -> 2 CTA/SM

#define WDEG 64

// ---------------- scratch (static device globals; no allocation) ----------------
__device__ float g_bufA[NN * DD];
__device__ float g_bufB[NN * DD];     // tf32-rounded x for layer 0, then hout(1)
__device__ float g_q[NN * DD];
__device__ float g_k[NN * DD];
__device__ float g_v[NN * DD];
__device__ float g_skip[NN * DD];
__device__ float g_Wt[LL * 4 * DD * DD];   // tf32-rounded weights [l][w][k][n]
__device__ float g_W5[LL * DD * 128];      // composed P-weight (cols 64..127 zero)
__device__ float g_b5[LL * 128];           // composed P-bias
__device__ float g_WeT[LL * DD * EDIMF];   // WeT[l][d*16+i] = We[l][i*DD+d]
__device__ float g_ef[EE * EDIMF];
__device__ float g_efcsr[EE * EDIMF];
__device__ float g_alpha[EE * HH];
__device__ float g_P[NN * HH * EDIMF];
__device__ int   g_rowptr[NN + 1];
__device__ int   g_cnt[NN];
__device__ int   g_cur[NN];
__device__ int   g_srcidx[EE];

// ---------------- helpers ----------------
__device__ __forceinline__ void cp16(uint32_t dst, const float* src) {
    asm volatile("cp.async.cg.shared.global [%0], [%1], 16;" ::"r"(dst),
                 "l"(__cvta_generic_to_global(src)));
}
__device__ __forceinline__ void cp_commit() { asm volatile("cp.async.commit_group;"); }
__device__ __forceinline__ void cp_wait1() { asm volatile("cp.async.wait_group 1;"); }

__device__ __forceinline__ uint32_t f2tf32(float f) {
    uint32_t u;
    asm("cvt.rna.tf32.f32 %0, %1;" : "=r"(u) : "f"(f));
    return u;
}
__device__ __forceinline__ float round_tf32(float f) { return __uint_as_float(f2tf32(f)); }

__device__ __forceinline__ void mma_tf32(float* c, const uint32_t* a, const uint32_t* b) {
    asm volatile(
        "mma.sync.aligned.m16n8k8.row.col.f32.tf32.tf32.f32 "
        "{%0,%1,%2,%3}, {%4,%5,%6,%7}, {%8,%9}, {%0,%1,%2,%3};"
        : "+f"(c[0]), "+f"(c[1]), "+f"(c[2]), "+f"(c[3])
        : "r"(a[0]), "r"(a[1]), "r"(a[2]), "r"(a[3]), "r"(b[0]), "r"(b[1]));
}

// ================= prep0: tf32-round all GEMM weights + x =================
#define WELEMS (LL * 4 * DD * DD / 4)
#define XELEMS (NN * DD / 4)
__global__ void round_kernel(const float* __restrict__ Wq, const float* __restrict__ Wk,
                             const float* __restrict__ Wv, const float* __restrict__ Ws,
                             const float* __restrict__ x,
                             float* __restrict__ Wt, float* __restrict__ xr) {
    int idx = blockIdx.x * blockDim.x + threadIdx.x;
    if (idx < WELEMS) {
        int z = idx / (DD * DD / 4);
        int rem = idx % (DD * DD / 4);
        int l = z >> 2, w = z & 3;
        const float* W = (w == 0 ? Wq : w == 1 ? Wk : w == 2 ? Wv : Ws) + (size_t)l * DD * DD;
        float4 val = ((const float4*)W)[rem];
        val.x = round_tf32(val.x); val.y = round_tf32(val.y);
        val.z = round_tf32(val.z); val.w = round_tf32(val.w);
        ((float4*)Wt)[idx] = val;
    } else if (idx < WELEMS + XELEMS) {
        int i = idx - WELEMS;
        float4 val = ((const float4*)x)[i];
        val.x = round_tf32(val.x); val.y = round_tf32(val.y);
        val.z = round_tf32(val.z); val.w = round_tf32(val.w);
        ((float4*)xr)[i] = val;
    }
}

// ================= prep1: edge count for CSR + build WeT =================
__global__ void count_kernel(const int* __restrict__ edge_index, int* __restrict__ cnt,
                             const float* __restrict__ We, float* __restrict__ WeT) {
    int idx = blockIdx.x * blockDim.x + threadIdx.x;
    if (idx < EE) atomicAdd(&cnt[edge_index[EE + idx]], 1);
    if (idx < LL * DD * EDIMF) {
        int l = idx / (DD * EDIMF);
        int rem = idx % (DD * EDIMF);
        int d = rem >> 4, i = rem & 15;
        WeT[idx] = We[(size_t)l * EDIMF * DD + (size_t)i * DD + d];
    }
}

// ================= prep2: compose W5 = Wq@Wp, b5 = bq@Wp (WeT path) =================
__global__ void __launch_bounds__(256) compose_kernel(
    const float* __restrict__ Wq, const float* __restrict__ bq,
    const float* __restrict__ WeT, float* __restrict__ W5, float* __restrict__ b5) {
    int l = blockIdx.x / 12;
    int k0 = (blockIdx.x % 12) * 64;
    int t = threadIdx.x;
    int j = t & 63, kl = t >> 6;
    int h = j >> 4, i = j & 15;
    const float* wq_base = Wq + (size_t)l * DD * DD + h * CC;
    const float* wet = WeT + (size_t)l * DD * EDIMF + (size_t)(h * CC) * 16 + i;
    float* W5l = W5 + (size_t)l * DD * 128;
    for (int kk = kl; kk < 64; kk += 4) {
        int k = k0 + kk;
        const float* wq = wq_base + (size_t)k * DD;
        float s0 = 0.f, s1 = 0.f, s2 = 0.f, s3 = 0.f;
#pragma unroll 4
        for (int c = 0; c < CC; c += 4) {
            s0 = fmaf(wq[c + 0], wet[(c + 0) * 16], s0);
            s1 = fmaf(wq[c + 1], wet[(c + 1) * 16], s1);
            s2 = fmaf(wq[c + 2], wet[(c + 2) * 16], s2);
            s3 = fmaf(wq[c + 3], wet[(c + 3) * 16], s3);
        }
        W5l[(size_t)k * 128 + j] = round_tf32((s0 + s1) + (s2 + s3));
        W5l[(size_t)k * 128 + 64 + j] = 0.f;
    }
    if (k0 == 0 && kl == 0) {
        const float* bb = bq + (size_t)l * DD + h * CC;
        float s = 0.f;
#pragma unroll 4
        for (int c = 0; c < CC; c++) s = fmaf(bb[c], wet[c * 16], s);
        b5[l * 128 + j] = s;
        b5[l * 128 + 64 + j] = 0.f;
    }
}

// ================= edge feature projection =================
__global__ void ef_kernel(const float* __restrict__ edge_attr, const float* __restrict__ rel_emb,
                          const float* __restrict__ W_edge, const float* __restrict__ b_edge,
                          float* __restrict__ ef) {
    __shared__ float sW[EDIMF * EDIMF];
    __shared__ float sB[EDIMF];
    __shared__ float sR[NRELC * (EDIMF - 1)];
    int t = threadIdx.x;
    if (t < EDIMF * EDIMF) sW[t] = W_edge[t];
    if (t < EDIMF) sB[t] = b_edge[t];
    if (t < NRELC * (EDIMF - 1)) sR[t] = rel_emb[t];
    __syncthreads();
    int e = blockIdx.x * blockDim.x + t;
    if (e >= EE) return;
    int r = (int)edge_attr[2 * e];
    r = min(max(r, 0), NRELC - 1);
    float feat[EDIMF];
#pragma unroll
    for (int i = 0; i < EDIMF - 1; i++) feat[i] = sR[r * (EDIMF - 1) + i];
    feat[EDIMF - 1] = edge_attr[2 * e + 1];
#pragma unroll
    for (int j = 0; j < EDIMF; j++) {
        float s = sB[j];
#pragma unroll
        for (int i = 0; i < EDIMF; i++) s += feat[i] * sW[i * EDIMF + j];
        ef[(size_t)e * EDIMF + j] = s;
    }
}

// ================= CSR scan =================
__global__ void scan_kernel(const int* __restrict__ cnt, int* __restrict__ rowptr) {
    __shared__ int s[1024];
    int t = threadIdx.x;
    int carry = 0;
    if (t == 0) rowptr[0] = 0;
    for (int base = 0; base < NN; base += 1024) {
        int i = base + t;
        s[t] = (i < NN) ? cnt[i] : 0;
        __syncthreads();
        for (int off = 1; off < 1024; off <<= 1) {
            int add = (t >= off) ? s[t - off] : 0;
            __syncthreads();
            s[t] += add;
            __syncthreads();
        }
        if (i < NN) rowptr[i + 1] = carry + s[t];
        int tot = s[1023];
        __syncthreads();
        carry += tot;
    }
}

__global__ void scatter_kernel(const int* __restrict__ edge_index, const int* __restrict__ rowptr,
                               int* __restrict__ cur, int* __restrict__ srcs,
                               const float* __restrict__ ef, float* __restrict__ efc) {
    int e = blockIdx.x * blockDim.x + threadIdx.x;
    if (e >= EE) return;
    int dst = edge_index[EE + e];
    int pos = rowptr[dst] + atomicAdd(&cur[dst], 1);
    srcs[pos] = edge_index[e];
    const float4* s = (const float4*)(ef + (size_t)e * EDIMF);
    float4* d = (float4*)(efc + (size_t)pos * EDIMF);
    d[0] = s[0]; d[1] = s[1]; d[2] = s[2]; d[3] = s[3];
}

// ================= fused Q/K/V/Skip/P GEMM via mma.sync tf32 =================
__global__ void __launch_bounds__(256, 2) gemm5_kernel(
    const float* __restrict__ A, const float* __restrict__ Wt,
    const float* __restrict__ W5, const float* __restrict__ b5,
    const float* __restrict__ b0, const float* __restrict__ b1,
    const float* __restrict__ b2, const float* __restrict__ b3,
    float* __restrict__ o0, float* __restrict__ o1,
    float* __restrict__ o2, float* __restrict__ o3,
    float* __restrict__ oP) {
    extern __shared__ float sm[];
    const int t = threadIdx.x;
    const int warp = t >> 5, lane = t & 31;
    const int g = lane >> 2, qd = lane & 3;
    const int w = blockIdx.x / 6;           // 0..4
    const int n0 = (w < 4) ? (blockIdx.x % 6) * BN : 0;
    const int m0 = blockIdx.y * BM;
    const int wm = warp & 1, wn = warp >> 1;

    const float* W;
    const float* bias;
    float* out;
    int ldw, ostride;
    if (w < 4) {
        W = Wt + (size_t)w * DD * DD;
        bias = (w == 0 ? b0 : w == 1 ? b1 : w == 2 ? b2 : b3);
        out = (w == 0 ? o0 : w == 1 ? o1 : w == 2 ? o2 : o3);
        ldw = DD; ostride = DD;
    } else {
        W = W5; bias = b5; out = oP;
        ldw = 128; ostride = 64;
    }

    uint32_t smb = (uint32_t)__cvta_generic_to_shared(sm);

    float c[4][4][4];
#pragma unroll
    for (int mi = 0; mi < 4; mi++)
#pragma unroll
        for (int ni = 0; ni < 4; ni++)
#pragma unroll
            for (int r = 0; r < 4; r++) c[mi][ni][r] = 0.f;

    auto load_stage = [&](int slot, int kt) {
        int k0 = kt * BK;
        uint32_t AsB = smb + (uint32_t)(slot * STAGE_FLOATS) * 4u;
        uint32_t BsB = AsB + AS_FLOATS * 4u;
#pragma unroll
        for (int s = 0; s < 4; s++) {
            int i = t + s * 256;
            int row = i >> 3, c4 = (i & 7) * 4;
            int grow = m0 + row;
            const float* src = A + (size_t)(grow < NN ? grow : 0) * DD + k0 + c4;
            cp16(AsB + (uint32_t)(row * SA + c4) * 4u, src);
        }
#pragma unroll
        for (int s = 0; s < 4; s++) {
            int i = t + s * 256;
            int row = i >> 5, c4 = (i & 31) * 4;
            const float* src = W + (size_t)(k0 + row) * ldw + n0 + c4;
            cp16(BsB + (uint32_t)(row * SB + c4) * 4u, src);
        }
    };

    load_stage(0, 0);
    cp_commit();
    load_stage(1, 1);
    cp_commit();

    for (int kt = 0; kt < NKT; kt++) {
        cp_wait1();
        __syncthreads();
        int cn = kt + 2;
        if (cn < NKT) load_stage(cn % GSTAGES, cn);
        cp_commit();
        const uint32_t* As = (const uint32_t*)(sm + (kt % GSTAGES) * STAGE_FLOATS);
        const uint32_t* Bs = As + AS_FLOATS;
#pragma unroll
        for (int ks = 0; ks < 4; ks++) {
            int k0s = ks * 8;
            uint32_t a[4][4], b[4][2];
#pragma unroll
            for (int mi = 0; mi < 4; mi++) {
                int mrow = wm * 64 + mi * 16 + g;
                const uint32_t* p = As + mrow * SA + k0s + qd;
                a[mi][0] = p[0];
                a[mi][1] = p[8 * SA];
                a[mi][2] = p[4];
                a[mi][3] = p[8 * SA + 4];
            }
#pragma unroll
            for (int ni = 0; ni < 4; ni++) {
                int ncol = wn * 32 + ni * 8 + g;
                const uint32_t* p = Bs + (k0s + qd) * SB + ncol;
                b[ni][0] = p[0];
                b[ni][1] = p[4 * SB];
            }
#pragma unroll
            for (int mi = 0; mi < 4; mi++)
#pragma unroll
                for (int ni = 0; ni < 4; ni++) mma_tf32(c[mi][ni], a[mi], b[ni]);
        }
    }

#pragma unroll
    for (int mi = 0; mi < 4; mi++) {
#pragma unroll
        for (int rh = 0; rh < 2; rh++) {
            int grow = m0 + wm * 64 + mi * 16 + rh * 8 + g;
            if (grow >= NN) continue;
            float* orow = out + (size_t)grow * ostride + n0;
#pragma unroll
            for (int ni = 0; ni < 4; ni++) {
                int col = wn * 32 + ni * 8 + 2 * qd;
                if (w == 4 && col >= 64) continue;   // P has 64 real cols
                float2 val;
                val.x = c[mi][ni][rh * 2 + 0] + bias[n0 + col];
                val.y = c[mi][ni][rh * 2 + 1] + bias[n0 + col + 1];
                *(float2*)(orow + col) = val;
            }
        }
    }
}

// ================= fused attention: warp per node (2-edge unrolled passes) =================
__global__ void __launch_bounds__(256) node_fused_kernel(
    const float* __restrict__ q, const float* __restrict__ kk, const float* __restrict__ v,
    const float* __restrict__ skip, const float* __restrict__ efc, const float* __restrict__ P,
    const int* __restrict__ rowptr, const int* __restrict__ srcs,
    const float* __restrict__ We, float* __restrict__ galpha,
    float* __restrict__ out, int gelu) {
    __shared__ float abuf[8][WDEG * HH];
    __shared__ float Ssm[8][2 * 32];
    const int wid = threadIdx.x >> 5, lane = threadIdx.x & 31;
    const int n = blockIdx.x * 8 + wid;
    if (n >= NN) return;
    const int start = rowptr[n], end = rowptr[n + 1];
    const int deg = end - start;
    const unsigned FULL = 0xffffffffu;
    const int h = lane >> 3, lg = lane & 7;
    const float scale = 0.07216878364870322f;  // 1/sqrt(192)

    float* wp = (deg <= WDEG) ? abuf[wid] : (galpha + (size_t)start * HH);

    // stage q row pre-scaled by 1/sqrt(C) (softmax shift-invariance makes P scaling exact too)
    const float4* qr = (const float4*)(q + (size_t)n * DD + h * CC);
    float4 qv[6];
#pragma unroll
    for (int j = 0; j < 6; j++) {
        float4 t4 = qr[lg + 8 * j];
        qv[j] = make_float4(t4.x * scale, t4.y * scale, t4.z * scale, t4.w * scale);
    }
    const float p0 = P[(size_t)n * (HH * EDIMF) + h * EDIMF + lg] * scale;
    const float p1 = P[(size_t)n * (HH * EDIMF) + h * EDIMF + lg + 8] * scale;

    // ---- pass A: alphas, 2 edges per iteration for MLP ----
    for (int base = 0; base < deg; base += 32) {
        int cnt = min(32, deg - base);
        int srcReg = (base + lane < deg) ? srcs[start + base + lane] : 0;
        int i = 0;
        for (; i + 2 <= cnt; i += 2) {
            int s0i = __shfl_sync(FULL, srcReg, i);
            int s1i = __shfl_sync(FULL, srcReg, i + 1);
            int e0 = start + base + i, e1 = e0 + 1;
            const float4* kr0 = (const float4*)(kk + (size_t)s0i * DD + h * CC);
            const float4* kr1 = (const float4*)(kk + (size_t)s1i * DD + h * CC);
            float4 kv0[6], kv1[6];
#pragma unroll
            for (int j = 0; j < 6; j++) kv0[j] = kr0[lg + 8 * j];
#pragma unroll
            for (int j = 0; j < 6; j++) kv1[j] = kr1[lg + 8 * j];
            float sA = 0.f, sB = 0.f;
#pragma unroll
            for (int j = 0; j < 6; j++) {
                sA = fmaf(qv[j].x, kv0[j].x, sA); sB = fmaf(qv[j].x, kv1[j].x, sB);
                sA = fmaf(qv[j].y, kv0[j].y, sA); sB = fmaf(qv[j].y, kv1[j].y, sB);
                sA = fmaf(qv[j].z, kv0[j].z, sA); sB = fmaf(qv[j].z, kv1[j].z, sB);
                sA = fmaf(qv[j].w, kv0[j].w, sA); sB = fmaf(qv[j].w, kv1[j].w, sB);
            }
            sA = fmaf(efc[(size_t)e0 * EDIMF + lg], p0, sA);
            sA = fmaf(efc[(size_t)e0 * EDIMF + lg + 8], p1, sA);
            sB = fmaf(efc[(size_t)e1 * EDIMF + lg], p0, sB);
            sB = fmaf(efc[(size_t)e1 * EDIMF + lg + 8], p1, sB);
#pragma unroll
            for (int o = 1; o <= 4; o <<= 1) {
                sA += __shfl_xor_sync(FULL, sA, o);
                sB += __shfl_xor_sync(FULL, sB, o);
            }
            if (lg == 0) {
                wp[(base + i) * HH + h] = sA;
                wp[(base + i + 1) * HH + h] = sB;
            }
        }
        if (i < cnt) {
            int s0i = __shfl_sync(FULL, srcReg, i);
            int e0 = start + base + i;
            const float4* kr0 = (const float4*)(kk + (size_t)s0i * DD + h * CC);
            float sA = 0.f;
#pragma unroll
            for (int j = 0; j < 6; j++) {
                float4 kv = kr0[lg + 8 * j];
                sA = fmaf(qv[j].x, kv.x, sA);
                sA = fmaf(qv[j].y, kv.y, sA);
                sA = fmaf(qv[j].z, kv.z, sA);
                sA = fmaf(qv[j].w, kv.w, sA);
            }
            sA = fmaf(efc[(size_t)e0 * EDIMF + lg], p0, sA);
            sA = fmaf(efc[(size_t)e0 * EDIMF + lg + 8], p1, sA);
#pragma unroll
            for (int o = 1; o <= 4; o <<= 1) sA += __shfl_xor_sync(FULL, sA, o);
            if (lg == 0) wp[(base + i) * HH + h] = sA;
        }
    }
    __syncwarp();

    // ---- softmax per head ----
    if (lane < HH) {
        float m = -1e30f;
        for (int i = 0; i < deg; i++) m = fmaxf(m, wp[i * HH + lane]);
        float ssum = 0.f;
        for (int i = 0; i < deg; i++) {
            float wv = expf(wp[i * HH + lane] - m);
            wp[i * HH + lane] = wv;
            ssum += wv;
        }
        float inv = 1.f / (ssum + 1e-16f);
        for (int i = 0; i < deg; i++) wp[i * HH + lane] *= inv;
    }
    __syncwarp();

    // ---- pass B: aggregate, 2 edges per iteration ----
    float acc[24];
#pragma unroll
    for (int j = 0; j < 24; j++) acc[j] = 0.f;
    float sa = 0.f, sb = 0.f;
    const int iA = lane & 15;
    const int hA = lane >> 4, hB = 2 + (lane >> 4);
    for (int base = 0; base < deg; base += 32) {
        int cnt = min(32, deg - base);
        int srcReg = (base + lane < deg) ? srcs[start + base + lane] : 0;
        int i = 0;
        for (; i + 2 <= cnt; i += 2) {
            int s0i = __shfl_sync(FULL, srcReg, i);
            int s1i = __shfl_sync(FULL, srcReg, i + 1);
            int idx0 = base + i, idx1 = idx0 + 1;
            const float* vr0 = v + (size_t)s0i * DD;
            const float* vr1 = v + (size_t)s1i * DD;
            float w00 = wp[idx0 * HH + 0], w01 = wp[idx0 * HH + 1];
            float w02 = wp[idx0 * HH + 2], w03 = wp[idx0 * HH + 3];
            float w10 = wp[idx1 * HH + 0], w11 = wp[idx1 * HH + 1];
            float w12 = wp[idx1 * HH + 2], w13 = wp[idx1 * HH + 3];
#pragma unroll
            for (int j = 0; j < 24; j++) {
                float wa = (j < 6) ? w00 : (j < 12) ? w01 : (j < 18) ? w02 : w03;
                float wb = (j < 6) ? w10 : (j < 12) ? w11 : (j < 18) ? w12 : w13;
                acc[j] = fmaf(wb, vr1[lane + 32 * j], fmaf(wa, vr0[lane + 32 * j], acc[j]));
            }
            float efA0 = efc[(size_t)(start + idx0) * EDIMF + iA];
            float efA1 = efc[(size_t)(start + idx1) * EDIMF + iA];
            sa = fmaf(wp[idx1 * HH + hA], efA1, fmaf(wp[idx0 * HH + hA], efA0, sa));
            sb = fmaf(wp[idx1 * HH + hB], efA1, fmaf(wp[idx0 * HH + hB], efA0, sb));
        }
        if (i < cnt) {
            int s0i = __shfl_sync(FULL, srcReg, i);
            int idx0 = base + i;
            const float* vr0 = v + (size_t)s0i * DD;
            float w00 = wp[idx0 * HH + 0], w01 = wp[idx0 * HH + 1];
            float w02 = wp[idx0 * HH + 2], w03 = wp[idx0 * HH + 3];
#pragma unroll
            for (int j = 0; j < 24; j++) {
                float wa = (j < 6) ? w00 : (j < 12) ? w01 : (j < 18) ? w02 : w03;
                acc[j] = fmaf(wa, vr0[lane + 32 * j], acc[j]);
            }
            float efA0 = efc[(size_t)(start + idx0) * EDIMF + iA];
            sa = fmaf(wp[idx0 * HH + hA], efA0, sa);
            sb = fmaf(wp[idx0 * HH + hB], efA0, sb);
        }
    }
    Ssm[wid][lane] = sa;
    Ssm[wid][lane + 32] = sb;
    __syncwarp();

    const float* sk = skip + (size_t)n * DD;
    float* orow = out + (size_t)n * DD;
#pragma unroll
    for (int j = 0; j < 24; j++) {
        int c = lane + 32 * j;
        int hh = j / 6;
        float val = acc[j];
#pragma unroll
        for (int i = 0; i < 16; i++)
            val = fmaf(Ssm[wid][hh * 16 + i], We[(size_t)i * DD + c], val);
        val += sk[c];
        if (gelu) {
            val = 0.5f * val * (1.f + erff(val * 0.7071067811865475f));
            val = round_tf32(val);
        }
        orow[c] = val;
    }
}

// ================= layernorm + global mean pool =================
__global__ void ln_pool_kernel(const float* __restrict__ h, float* __restrict__ out) {
    __shared__ float red[256];
    int t = threadIdx.x;
    float acc0 = 0.f, acc1 = 0.f, acc2 = 0.f;
    for (int n = blockIdx.x; n < NN; n += gridDim.x) {
        const float* row = h + (size_t)n * DD;
        float v0 = row[t], v1 = row[t + 256], v2 = row[t + 512];
        red[t] = v0 + v1 + v2;
        __syncthreads();
        for (int off = 128; off > 0; off >>= 1) {
            if (t < off) red[t] += red[t + off];
            __syncthreads();
        }
        float mu = red[0] * (1.f / DD);
        __syncthreads();
        float d0 = v0 - mu, d1 = v1 - mu, d2 = v2 - mu;
        red[t] = d0 * d0 + d1 * d1 + d2 * d2;
        __syncthreads();
        for (int off = 128; off > 0; off >>= 1) {
            if (t < off) red[t] += red[t + off];
            __syncthreads();
        }
        float rstd = rsqrtf(red[0] * (1.f / DD) + 1e-5f);
        __syncthreads();
        acc0 += d0 * rstd;
        acc1 += d1 * rstd;
        acc2 += d2 * rstd;
    }
    atomicAdd(&out[t], acc0);
    atomicAdd(&out[t + 256], acc1);
    atomicAdd(&out[t + 512], acc2);
}

__global__ void ln_final_kernel(float* __restrict__ out, const float* __restrict__ g,
                                const float* __restrict__ b) {
    int c = threadIdx.x + blockIdx.x * blockDim.x;
    if (c < DD) out[c] = out[c] * g[c] * (1.f / NN) + b[c];
}

// ================= launch =================
extern "C" void kernel_launch(void* const* d_in, const int* in_sizes, int n_in,
                              void* d_out, int out_size) {
    const float* x          = (const float*)d_in[0];
    const float* edge_attr  = (const float*)d_in[1];
    const int*   edge_index = (const int*)d_in[2];
    const float* rel_emb    = (const float*)d_in[3];
    const float* W_edge     = (const float*)d_in[4];
    const float* b_edge     = (const float*)d_in[5];
    const float* Wk         = (const float*)d_in[6];
    const float* bk         = (const float*)d_in[7];
    const float* Wq         = (const float*)d_in[8];
    const float* bq         = (const float*)d_in[9];
    const float* Wv         = (const float*)d_in[10];
    const float* bv         = (const float*)d_in[11];
    const float* We         = (const float*)d_in[12];
    const float* Wskip      = (const float*)d_in[13];
    const float* bskip      = (const float*)d_in[14];
    const float* ln_g       = (const float*)d_in[15];
    const float* ln_b       = (const float*)d_in[16];
    float* out = (float*)d_out;

    float *bufA, *bufB, *q, *k, *v, *skip, *ef, *efc, *alpha, *P, *Wt, *W5, *b5, *WeT;
    int *rowptr, *cnt, *cur, *srcidx;
    cudaGetSymbolAddress((void**)&bufA, g_bufA);
    cudaGetSymbolAddress((void**)&bufB, g_bufB);
    cudaGetSymbolAddress((void**)&q, g_q);
    cudaGetSymbolAddress((void**)&k, g_k);
    cudaGetSymbolAddress((void**)&v, g_v);
    cudaGetSymbolAddress((void**)&skip, g_skip);
    cudaGetSymbolAddress((void**)&ef, g_ef);
    cudaGetSymbolAddress((void**)&efc, g_efcsr);
    cudaGetSymbolAddress((void**)&alpha, g_alpha);
    cudaGetSymbolAddress((void**)&P, g_P);
    cudaGetSymbolAddress((void**)&Wt, g_Wt);
    cudaGetSymbolAddress((void**)&W5, g_W5);
    cudaGetSymbolAddress((void**)&b5, g_b5);
    cudaGetSymbolAddress((void**)&WeT, g_WeT);
    cudaGetSymbolAddress((void**)&rowptr, g_rowptr);
    cudaGetSymbolAddress((void**)&cnt, g_cnt);
    cudaGetSymbolAddress((void**)&cur, g_cur);
    cudaGetSymbolAddress((void**)&srcidx, g_srcidx);

    cudaFuncSetAttribute(gemm5_kernel, cudaFuncAttributeMaxDynamicSharedMemorySize, GEMM_SMEM);

    cudaMemsetAsync(cnt, 0, NN * sizeof(int));
    cudaMemsetAsync(cur, 0, NN * sizeof(int));
    // #1..#3 prep; gemm5(L0) = kernel #4 = ncu capture slot
    round_kernel<<<(WELEMS + XELEMS + 255) / 256, 256>>>(Wq, Wk, Wv, Wskip, x, Wt, bufB);    // #1
    count_kernel<<<(EE + 255) / 256, 256>>>(edge_index, cnt, We, WeT);                        // #2
    compose_kernel<<<LL * 12, 256>>>(Wq, bq, WeT, W5, b5);                                    // #3

    const float* hin = bufB;   // tf32-rounded x
    for (int l = 0; l < LL; l++) {
        const float* We_l = We + (size_t)l * EDIMF * DD;
        gemm5_kernel<<<dim3(25, (NN + BM - 1) / BM), 256, GEMM_SMEM>>>(                       // #4 (l=0)
            hin, Wt + (size_t)l * 4 * DD * DD,
            W5 + (size_t)l * DD * 128, b5 + (size_t)l * 128,
            bq + (size_t)l * DD, bk + (size_t)l * DD, bv + (size_t)l * DD, bskip + (size_t)l * DD,
            q, k, v, skip, P);
        if (l == 0) {
            scan_kernel<<<1, 1024>>>(cnt, rowptr);
            ef_kernel<<<(EE + 255) / 256, 256>>>(edge_attr, rel_emb, W_edge, b_edge, ef);
            scatter_kernel<<<(EE + 255) / 256, 256>>>(edge_index, rowptr, cur, srcidx, ef, efc);
        }
        float* hout = (l & 1) ? bufB : bufA;
        node_fused_kernel<<<(NN + 7) / 8, 256>>>(q, k, v, skip, efc, P, rowptr, srcidx, We_l,
                                                 alpha, hout, (l < LL - 1) ? 1 : 0);
        hin = hout;
    }

    cudaMemsetAsync(out, 0, DD * sizeof(float));
    ln_pool_kernel<<<1024, 256>>>(hin, out);
    ln_final_kernel<<<3, 256>>>(out, ln_g, ln_b);
}

// round 16
// speedup vs baseline: 1.0467x; 1.0467x over previous
#include <cuda_runtime.h>
#include <cstdint>

#define NN 10000
#define EE 100000
#define DD 768
#define HH 4
#define CC 192
#define LL 3
#define EDIMF 16
#define NRELC 10

#define BM 128
#define BN 128
#define BK 32
#define NKT (DD / BK)
#define GSTAGES 3
#define SA 36
#define SB 136
#define AS_FLOATS (BM * SA)
#define BS_FLOATS (BK * SB)
#define STAGE_FLOATS (AS_FLOATS + BS_FLOATS)
#define GEMM_SMEM (GSTAGES * STAGE_FLOATS * 4)   // ~105 KB -> 2 CTA/SM

#define WDEG 64

// ---------------- scratch ----------------
__device__ float g_bufA[NN * DD];
__device__ float g_bufB[NN * DD];
__device__ float g_q[NN * DD];
__device__ float g_k[NN * DD];
__device__ float g_v[NN * DD];
__device__ float g_skip[NN * DD];
__device__ float g_Wt[LL * 4 * DD * DD];
__device__ float g_W5[LL * DD * 128];
__device__ float g_b5[LL * 128];
__device__ float g_WeT[LL * DD * EDIMF];
__device__ float g_ef[EE * EDIMF];
__device__ float g_efcsr[EE * EDIMF];
__device__ float g_alpha[EE * HH];
__device__ float g_P[NN * HH * EDIMF];
__device__ int   g_rowptr[NN + 1];
__device__ int   g_cnt[NN];
__device__ int   g_cur[NN];
__device__ int   g_srcidx[EE];

// ---------------- helpers ----------------
__device__ __forceinline__ void cp16(uint32_t dst, const float* src) {
    asm volatile("cp.async.cg.shared.global [%0], [%1], 16;" ::"r"(dst),
                 "l"(__cvta_generic_to_global(src)));
}
__device__ __forceinline__ void cp_commit() { asm volatile("cp.async.commit_group;"); }
__device__ __forceinline__ void cp_wait1() { asm volatile("cp.async.wait_group 1;"); }

__device__ __forceinline__ uint32_t f2tf32(float f) {
    uint32_t u;
    asm("cvt.rna.tf32.f32 %0, %1;" : "=r"(u) : "f"(f));
    return u;
}
__device__ __forceinline__ float round_tf32(float f) { return __uint_as_float(f2tf32(f)); }

__device__ __forceinline__ void mma_tf32(float* c, const uint32_t* a, const uint32_t* b) {
    asm volatile(
        "mma.sync.aligned.m16n8k8.row.col.f32.tf32.tf32.f32 "
        "{%0,%1,%2,%3}, {%4,%5,%6,%7}, {%8,%9}, {%0,%1,%2,%3};"
        : "+f"(c[0]), "+f"(c[1]), "+f"(c[2]), "+f"(c[3])
        : "r"(a[0]), "r"(a[1]), "r"(a[2]), "r"(a[3]), "r"(b[0]), "r"(b[1]));
}

// ================= megaprep: round(W,x) + CSR count + WeT + ef in one launch =================
#define WELEMS (LL * 4 * DD * DD / 4)
#define XELEMS (NN * DD / 4)
#define NB_W  ((WELEMS + 255) / 256)
#define NB_X  ((XELEMS + 255) / 256)
#define NB_CNT ((EE + 255) / 256)
#define NB_WET ((LL * DD * EDIMF + 255) / 256)
#define NB_EF ((EE + 255) / 256)
#define NB_TOTAL (NB_W + NB_X + NB_CNT + NB_WET + NB_EF)

__global__ void __launch_bounds__(256) megaprep_kernel(
    const float* __restrict__ Wq, const float* __restrict__ Wk,
    const float* __restrict__ Wv, const float* __restrict__ Ws,
    const float* __restrict__ x, float* __restrict__ Wt, float* __restrict__ xr,
    const int* __restrict__ edge_index, int* __restrict__ cnt,
    const float* __restrict__ We, float* __restrict__ WeT,
    const float* __restrict__ edge_attr, const float* __restrict__ rel_emb,
    const float* __restrict__ W_edge, const float* __restrict__ b_edge,
    float* __restrict__ ef) {
    int b = blockIdx.x;
    int t = threadIdx.x;
    if (b < NB_W) {
        int idx = b * 256 + t;
        if (idx < WELEMS) {
            int z = idx / (DD * DD / 4);
            int rem = idx % (DD * DD / 4);
            int l = z >> 2, w = z & 3;
            const float* W = (w == 0 ? Wq : w == 1 ? Wk : w == 2 ? Wv : Ws) + (size_t)l * DD * DD;
            float4 val = ((const float4*)W)[rem];
            val.x = round_tf32(val.x); val.y = round_tf32(val.y);
            val.z = round_tf32(val.z); val.w = round_tf32(val.w);
            ((float4*)Wt)[idx] = val;
        }
        return;
    }
    b -= NB_W;
    if (b < NB_X) {
        int idx = b * 256 + t;
        if (idx < XELEMS) {
            float4 val = ((const float4*)x)[idx];
            val.x = round_tf32(val.x); val.y = round_tf32(val.y);
            val.z = round_tf32(val.z); val.w = round_tf32(val.w);
            ((float4*)xr)[idx] = val;
        }
        return;
    }
    b -= NB_X;
    if (b < NB_CNT) {
        int e = b * 256 + t;
        if (e < EE) atomicAdd(&cnt[edge_index[EE + e]], 1);
        return;
    }
    b -= NB_CNT;
    if (b < NB_WET) {
        int idx = b * 256 + t;
        if (idx < LL * DD * EDIMF) {
            int l = idx / (DD * EDIMF);
            int rem = idx % (DD * EDIMF);
            int d = rem >> 4, i = rem & 15;
            WeT[idx] = We[(size_t)l * EDIMF * DD + (size_t)i * DD + d];
        }
        return;
    }
    b -= NB_WET;
    {
        __shared__ float sW[EDIMF * EDIMF];
        __shared__ float sB[EDIMF];
        __shared__ float sR[NRELC * (EDIMF - 1)];
        if (t < EDIMF * EDIMF) sW[t] = W_edge[t];
        if (t < EDIMF) sB[t] = b_edge[t];
        if (t < NRELC * (EDIMF - 1)) sR[t] = rel_emb[t];
        __syncthreads();
        int e = b * 256 + t;
        if (e >= EE) return;
        int r = (int)edge_attr[2 * e];
        r = min(max(r, 0), NRELC - 1);
        float feat[EDIMF];
#pragma unroll
        for (int i = 0; i < EDIMF - 1; i++) feat[i] = sR[r * (EDIMF - 1) + i];
        feat[EDIMF - 1] = edge_attr[2 * e + 1];
#pragma unroll
        for (int j = 0; j < EDIMF; j++) {
            float s = sB[j];
#pragma unroll
            for (int i = 0; i < EDIMF; i++) s += feat[i] * sW[i * EDIMF + j];
            ef[(size_t)e * EDIMF + j] = s;
        }
    }
}

// ================= scan (block 0) + compose (blocks 1..36), 1024 threads =================
__global__ void __launch_bounds__(1024) scan_compose_kernel(
    const int* __restrict__ cnt, int* __restrict__ rowptr,
    const float* __restrict__ Wq, const float* __restrict__ bq,
    const float* __restrict__ WeT, float* __restrict__ W5, float* __restrict__ b5) {
    int t = threadIdx.x;
    if (blockIdx.x == 0) {
        __shared__ int s[1024];
        int carry = 0;
        if (t == 0) rowptr[0] = 0;
        for (int base = 0; base < NN; base += 1024) {
            int i = base + t;
            s[t] = (i < NN) ? cnt[i] : 0;
            __syncthreads();
            for (int off = 1; off < 1024; off <<= 1) {
                int add = (t >= off) ? s[t - off] : 0;
                __syncthreads();
                s[t] += add;
                __syncthreads();
            }
            if (i < NN) rowptr[i + 1] = carry + s[t];
            int tot = s[1023];
            __syncthreads();
            carry += tot;
        }
        return;
    }
    int cb = blockIdx.x - 1;            // 0..35
    int l = cb / 12;
    int k0 = (cb % 12) * 64;
    int j = t & 63, kl = t >> 6;        // kl 0..15
    int h = j >> 4, i = j & 15;
    const float* wq_base = Wq + (size_t)l * DD * DD + h * CC;
    const float* wet = WeT + (size_t)l * DD * EDIMF + (size_t)(h * CC) * 16 + i;
    float* W5l = W5 + (size_t)l * DD * 128;
    for (int kk = kl; kk < 64; kk += 16) {
        int k = k0 + kk;
        const float* wq = wq_base + (size_t)k * DD;
        float s0 = 0.f, s1 = 0.f, s2 = 0.f, s3 = 0.f;
#pragma unroll 4
        for (int c = 0; c < CC; c += 4) {
            s0 = fmaf(wq[c + 0], wet[(c + 0) * 16], s0);
            s1 = fmaf(wq[c + 1], wet[(c + 1) * 16], s1);
            s2 = fmaf(wq[c + 2], wet[(c + 2) * 16], s2);
            s3 = fmaf(wq[c + 3], wet[(c + 3) * 16], s3);
        }
        W5l[(size_t)k * 128 + j] = round_tf32((s0 + s1) + (s2 + s3));
        W5l[(size_t)k * 128 + 64 + j] = 0.f;
    }
    if (k0 == 0 && kl == 0) {
        const float* bb = bq + (size_t)l * DD + h * CC;
        float s = 0.f;
#pragma unroll 4
        for (int c = 0; c < CC; c++) s = fmaf(bb[c], wet[c * 16], s);
        b5[l * 128 + j] = s;
        b5[l * 128 + 64 + j] = 0.f;
    }
}

// ================= fused Q/K/V/Skip/P GEMM; bx==25 blocks do the CSR scatter (L0 only) =================
__global__ void __launch_bounds__(256, 2) gemm5_kernel(
    const float* __restrict__ A, const float* __restrict__ Wt,
    const float* __restrict__ W5, const float* __restrict__ b5,
    const float* __restrict__ b0, const float* __restrict__ b1,
    const float* __restrict__ b2, const float* __restrict__ b3,
    float* __restrict__ o0, float* __restrict__ o1,
    float* __restrict__ o2, float* __restrict__ o3,
    float* __restrict__ oP,
    int do_scatter, const int* __restrict__ edge_index, const int* __restrict__ rowptr,
    int* __restrict__ cur, int* __restrict__ srcs,
    const float* __restrict__ ef, float* __restrict__ efc) {
    extern __shared__ float sm[];
    const int t = threadIdx.x;
    if (blockIdx.x == 25) {
        if (do_scatter) {
            for (int e = blockIdx.y * 256 + t; e < EE; e += 79 * 256) {
                int dst = edge_index[EE + e];
                int pos = rowptr[dst] + atomicAdd(&cur[dst], 1);
                srcs[pos] = edge_index[e];
                const float4* s = (const float4*)(ef + (size_t)e * EDIMF);
                float4* d = (float4*)(efc + (size_t)pos * EDIMF);
                d[0] = s[0]; d[1] = s[1]; d[2] = s[2]; d[3] = s[3];
            }
        }
        return;
    }
    const int warp = t >> 5, lane = t & 31;
    const int g = lane >> 2, qd = lane & 3;
    const int w = blockIdx.x / 6;           // 0..4
    const int n0 = (w < 4) ? (blockIdx.x % 6) * BN : 0;
    const int m0 = blockIdx.y * BM;
    const int wm = warp & 1, wn = warp >> 1;

    const float* W;
    const float* bias;
    float* out;
    int ldw, ostride;
    if (w < 4) {
        W = Wt + (size_t)w * DD * DD;
        bias = (w == 0 ? b0 : w == 1 ? b1 : w == 2 ? b2 : b3);
        out = (w == 0 ? o0 : w == 1 ? o1 : w == 2 ? o2 : o3);
        ldw = DD; ostride = DD;
    } else {
        W = W5; bias = b5; out = oP;
        ldw = 128; ostride = 64;
    }

    uint32_t smb = (uint32_t)__cvta_generic_to_shared(sm);

    float c[4][4][4];
#pragma unroll
    for (int mi = 0; mi < 4; mi++)
#pragma unroll
        for (int ni = 0; ni < 4; ni++)
#pragma unroll
            for (int r = 0; r < 4; r++) c[mi][ni][r] = 0.f;

    auto load_stage = [&](int slot, int kt) {
        int k0 = kt * BK;
        uint32_t AsB = smb + (uint32_t)(slot * STAGE_FLOATS) * 4u;
        uint32_t BsB = AsB + AS_FLOATS * 4u;
#pragma unroll
        for (int s = 0; s < 4; s++) {
            int i = t + s * 256;
            int row = i >> 3, c4 = (i & 7) * 4;
            int grow = m0 + row;
            const float* src = A + (size_t)(grow < NN ? grow : 0) * DD + k0 + c4;
            cp16(AsB + (uint32_t)(row * SA + c4) * 4u, src);
        }
#pragma unroll
        for (int s = 0; s < 4; s++) {
            int i = t + s * 256;
            int row = i >> 5, c4 = (i & 31) * 4;
            const float* src = W + (size_t)(k0 + row) * ldw + n0 + c4;
            cp16(BsB + (uint32_t)(row * SB + c4) * 4u, src);
        }
    };

    load_stage(0, 0);
    cp_commit();
    load_stage(1, 1);
    cp_commit();

    for (int kt = 0; kt < NKT; kt++) {
        cp_wait1();
        __syncthreads();
        int cn = kt + 2;
        if (cn < NKT) load_stage(cn % GSTAGES, cn);
        cp_commit();
        const uint32_t* As = (const uint32_t*)(sm + (kt % GSTAGES) * STAGE_FLOATS);
        const uint32_t* Bs = As + AS_FLOATS;
#pragma unroll
        for (int ks = 0; ks < 4; ks++) {
            int k0s = ks * 8;
            uint32_t a[4][4], b[4][2];
#pragma unroll
            for (int mi = 0; mi < 4; mi++) {
                int mrow = wm * 64 + mi * 16 + g;
                const uint32_t* p = As + mrow * SA + k0s + qd;
                a[mi][0] = p[0];
                a[mi][1] = p[8 * SA];
                a[mi][2] = p[4];
                a[mi][3] = p[8 * SA + 4];
            }
#pragma unroll
            for (int ni = 0; ni < 4; ni++) {
                int ncol = wn * 32 + ni * 8 + g;
                const uint32_t* p = Bs + (k0s + qd) * SB + ncol;
                b[ni][0] = p[0];
                b[ni][1] = p[4 * SB];
            }
#pragma unroll
            for (int mi = 0; mi < 4; mi++)
#pragma unroll
                for (int ni = 0; ni < 4; ni++) mma_tf32(c[mi][ni], a[mi], b[ni]);
        }
    }

#pragma unroll
    for (int mi = 0; mi < 4; mi++) {
#pragma unroll
        for (int rh = 0; rh < 2; rh++) {
            int grow = m0 + wm * 64 + mi * 16 + rh * 8 + g;
            if (grow >= NN) continue;
            float* orow = out + (size_t)grow * ostride + n0;
#pragma unroll
            for (int ni = 0; ni < 4; ni++) {
                int col = wn * 32 + ni * 8 + 2 * qd;
                if (w == 4 && col >= 64) continue;
                float2 val;
                val.x = c[mi][ni][rh * 2 + 0] + bias[n0 + col];
                val.y = c[mi][ni][rh * 2 + 1] + bias[n0 + col + 1];
                *(float2*)(orow + col) = val;
            }
        }
    }
}

// ================= fused attention: warp per node (R14 best version) =================
__global__ void __launch_bounds__(256) node_fused_kernel(
    const float* __restrict__ q, const float* __restrict__ kk, const float* __restrict__ v,
    const float* __restrict__ skip, const float* __restrict__ efc, const float* __restrict__ P,
    const int* __restrict__ rowptr, const int* __restrict__ srcs,
    const float* __restrict__ We, float* __restrict__ galpha,
    float* __restrict__ out, int gelu) {
    __shared__ float abuf[8][WDEG * HH];
    __shared__ float Ssm[8][2 * 32];
    const int wid = threadIdx.x >> 5, lane = threadIdx.x & 31;
    const int n = blockIdx.x * 8 + wid;
    if (n >= NN) return;
    const int start = rowptr[n], end = rowptr[n + 1];
    const int deg = end - start;
    const unsigned FULL = 0xffffffffu;
    const int h = lane >> 3, lg = lane & 7;

    float* wp = (deg <= WDEG) ? abuf[wid] : (galpha + (size_t)start * HH);

    const float4* qr = (const float4*)(q + (size_t)n * DD + h * CC);
    float4 qv[6];
#pragma unroll
    for (int j = 0; j < 6; j++) qv[j] = qr[lg + 8 * j];
    const float p0 = P[(size_t)n * (HH * EDIMF) + h * EDIMF + lg];
    const float p1 = P[(size_t)n * (HH * EDIMF) + h * EDIMF + lg + 8];

    for (int base = 0; base < deg; base += 32) {
        int cnt = min(32, deg - base);
        int srcReg = (base + lane < deg) ? srcs[start + base + lane] : 0;
        for (int i = 0; i < cnt; i++) {
            int src = __shfl_sync(FULL, srcReg, i);
            int e = start + base + i;
            const float4* kr = (const float4*)(kk + (size_t)src * DD + h * CC);
            float s = 0.f;
#pragma unroll
            for (int j = 0; j < 6; j++) {
                float4 kv = kr[lg + 8 * j];
                s = fmaf(qv[j].x, kv.x, s);
                s = fmaf(qv[j].y, kv.y, s);
                s = fmaf(qv[j].z, kv.z, s);
                s = fmaf(qv[j].w, kv.w, s);
            }
            s = fmaf(efc[(size_t)e * EDIMF + lg], p0, s);
            s = fmaf(efc[(size_t)e * EDIMF + lg + 8], p1, s);
            s += __shfl_xor_sync(FULL, s, 1);
            s += __shfl_xor_sync(FULL, s, 2);
            s += __shfl_xor_sync(FULL, s, 4);
            if (lg == 0) wp[(base + i) * HH + h] = s * 0.07216878364870322f;
        }
    }
    __syncwarp();

    if (lane < HH) {
        float m = -1e30f;
        for (int i = 0; i < deg; i++) m = fmaxf(m, wp[i * HH + lane]);
        float ssum = 0.f;
        for (int i = 0; i < deg; i++) {
            float wv = expf(wp[i * HH + lane] - m);
            wp[i * HH + lane] = wv;
            ssum += wv;
        }
        float inv = 1.f / (ssum + 1e-16f);
        for (int i = 0; i < deg; i++) wp[i * HH + lane] *= inv;
    }
    __syncwarp();

    float acc[24];
#pragma unroll
    for (int j = 0; j < 24; j++) acc[j] = 0.f;
    float sa = 0.f, sb = 0.f;
    const int iA = lane & 15;
    const int hA = lane >> 4, hB = 2 + (lane >> 4);
    for (int base = 0; base < deg; base += 32) {
        int cnt = min(32, deg - base);
        int srcReg = (base + lane < deg) ? srcs[start + base + lane] : 0;
        for (int i = 0; i < cnt; i++) {
            int src = __shfl_sync(FULL, srcReg, i);
            int idx = base + i;
            const float* vr = v + (size_t)src * DD;
            float w0 = wp[idx * HH + 0];
            float w1 = wp[idx * HH + 1];
            float w2 = wp[idx * HH + 2];
            float w3 = wp[idx * HH + 3];
#pragma unroll
            for (int j = 0; j < 24; j++) {
                float wj = (j < 6) ? w0 : (j < 12) ? w1 : (j < 18) ? w2 : w3;
                acc[j] = fmaf(wj, vr[lane + 32 * j], acc[j]);
            }
            float efA = efc[(size_t)(start + idx) * EDIMF + iA];
            sa = fmaf(wp[idx * HH + hA], efA, sa);
            sb = fmaf(wp[idx * HH + hB], efA, sb);
        }
    }
    Ssm[wid][lane] = sa;
    Ssm[wid][lane + 32] = sb;
    __syncwarp();

    const float* sk = skip + (size_t)n * DD;
    float* orow = out + (size_t)n * DD;
#pragma unroll
    for (int j = 0; j < 24; j++) {
        int c = lane + 32 * j;
        int hh = j / 6;
        float val = acc[j];
#pragma unroll
        for (int i = 0; i < 16; i++)
            val = fmaf(Ssm[wid][hh * 16 + i], We[(size_t)i * DD + c], val);
        val += sk[c];
        if (gelu) {
            val = 0.5f * val * (1.f + erff(val * 0.7071067811865475f));
            val = round_tf32(val);
        }
        orow[c] = val;
    }
}

// ================= layernorm + global mean pool =================
__global__ void ln_pool_kernel(const float* __restrict__ h, float* __restrict__ out) {
    __shared__ float red[256];
    int t = threadIdx.x;
    float acc0 = 0.f, acc1 = 0.f, acc2 = 0.f;
    for (int n = blockIdx.x; n < NN; n += gridDim.x) {
        const float* row = h + (size_t)n * DD;
        float v0 = row[t], v1 = row[t + 256], v2 = row[t + 512];
        red[t] = v0 + v1 + v2;
        __syncthreads();
        for (int off = 128; off > 0; off >>= 1) {
            if (t < off) red[t] += red[t + off];
            __syncthreads();
        }
        float mu = red[0] * (1.f / DD);
        __syncthreads();
        float d0 = v0 - mu, d1 = v1 - mu, d2 = v2 - mu;
        red[t] = d0 * d0 + d1 * d1 + d2 * d2;
        __syncthreads();
        for (int off = 128; off > 0; off >>= 1) {
            if (t < off) red[t] += red[t + off];
            __syncthreads();
        }
        float rstd = rsqrtf(red[0] * (1.f / DD) + 1e-5f);
        __syncthreads();
        acc0 += d0 * rstd;
        acc1 += d1 * rstd;
        acc2 += d2 * rstd;
    }
    atomicAdd(&out[t], acc0);
    atomicAdd(&out[t + 256], acc1);
    atomicAdd(&out[t + 512], acc2);
}

__global__ void ln_final_kernel(float* __restrict__ out, const float* __restrict__ g,
                                const float* __restrict__ b) {
    int c = threadIdx.x + blockIdx.x * blockDim.x;
    if (c < DD) out[c] = out[c] * g[c] * (1.f / NN) + b[c];
}

// ================= launch =================
extern "C" void kernel_launch(void* const* d_in, const int* in_sizes, int n_in,
                              void* d_out, int out_size) {
    const float* x          = (const float*)d_in[0];
    const float* edge_attr  = (const float*)d_in[1];
    const int*   edge_index = (const int*)d_in[2];
    const float* rel_emb    = (const float*)d_in[3];
    const float* W_edge     = (const float*)d_in[4];
    const float* b_edge     = (const float*)d_in[5];
    const float* Wk         = (const float*)d_in[6];
    const float* bk         = (const float*)d_in[7];
    const float* Wq         = (const float*)d_in[8];
    const float* bq         = (const float*)d_in[9];
    const float* Wv         = (const float*)d_in[10];
    const float* bv         = (const float*)d_in[11];
    const float* We         = (const float*)d_in[12];
    const float* Wskip      = (const float*)d_in[13];
    const float* bskip      = (const float*)d_in[14];
    const float* ln_g       = (const float*)d_in[15];
    const float* ln_b       = (const float*)d_in[16];
    float* out = (float*)d_out;

    float *bufA, *bufB, *q, *k, *v, *skip, *ef, *efc, *alpha, *P, *Wt, *W5, *b5, *WeT;
    int *rowptr, *cnt, *cur, *srcidx;
    cudaGetSymbolAddress((void**)&bufA, g_bufA);
    cudaGetSymbolAddress((void**)&bufB, g_bufB);
    cudaGetSymbolAddress((void**)&q, g_q);
    cudaGetSymbolAddress((void**)&k, g_k);
    cudaGetSymbolAddress((void**)&v, g_v);
    cudaGetSymbolAddress((void**)&skip, g_skip);
    cudaGetSymbolAddress((void**)&ef, g_ef);
    cudaGetSymbolAddress((void**)&efc, g_efcsr);
    cudaGetSymbolAddress((void**)&alpha, g_alpha);
    cudaGetSymbolAddress((void**)&P, g_P);
    cudaGetSymbolAddress((void**)&Wt, g_Wt);
    cudaGetSymbolAddress((void**)&W5, g_W5);
    cudaGetSymbolAddress((void**)&b5, g_b5);
    cudaGetSymbolAddress((void**)&WeT, g_WeT);
    cudaGetSymbolAddress((void**)&rowptr, g_rowptr);
    cudaGetSymbolAddress((void**)&cnt, g_cnt);
    cudaGetSymbolAddress((void**)&cur, g_cur);
    cudaGetSymbolAddress((void**)&srcidx, g_srcidx);

    cudaFuncSetAttribute(gemm5_kernel, cudaFuncAttributeMaxDynamicSharedMemorySize, GEMM_SMEM);

    cudaMemsetAsync(cnt, 0, NN * sizeof(int));
    cudaMemsetAsync(cur, 0, NN * sizeof(int));
    // #1 megaprep, #2 scan+compose, #3 gemm5(L0, +scatter), #4 node_fused(L0) <- ncu slot
    megaprep_kernel<<<NB_TOTAL, 256>>>(Wq, Wk, Wv, Wskip, x, Wt, bufB,
                                       edge_index, cnt, We, WeT,
                                       edge_attr, rel_emb, W_edge, b_edge, ef);
    scan_compose_kernel<<<1 + LL * 12, 1024>>>(cnt, rowptr, Wq, bq, WeT, W5, b5);

    const float* hin = bufB;   // tf32-rounded x
    for (int l = 0; l < LL; l++) {
        const float* We_l = We + (size_t)l * EDIMF * DD;
        gemm5_kernel<<<dim3(26, (NN + BM - 1) / BM), 256, GEMM_SMEM>>>(
            hin, Wt + (size_t)l * 4 * DD * DD,
            W5 + (size_t)l * DD * 128, b5 + (size_t)l * 128,
            bq + (size_t)l * DD, bk + (size_t)l * DD, bv + (size_t)l * DD, bskip + (size_t)l * DD,
            q, k, v, skip, P,
            (l == 0) ? 1 : 0, edge_index, rowptr, cur, srcidx, ef, efc);
        float* hout = (l & 1) ? bufB : bufA;
        node_fused_kernel<<<(NN + 7) / 8, 256>>>(q, k, v, skip, efc, P, rowptr, srcidx, We_l,
                                                 alpha, hout, (l < LL - 1) ? 1 : 0);
        hin = hout;
    }

    cudaMemsetAsync(out, 0, DD * sizeof(float));
    ln_pool_kernel<<<1024, 256>>>(hin, out);
    ln_final_kernel<<<3, 256>>>(out, ln_g, ln_b);
}

// round 17
// speedup vs baseline: 1.0657x; 1.0181x over previous
#include <cuda_runtime.h>
#include <cstdint>

#define NN 10000
#define EE 100000
#define DD 768
#define HH 4
#define CC 192
#define LL 3
#define EDIMF 16
#define NRELC 10

#define BM 128
#define BN 128
#define BK 32
#define NKT (DD / BK)
#define GSTAGES 3
#define SA 36
#define SB 136
#define AS_FLOATS (BM * SA)
#define BS_FLOATS (BK * SB)
#define STAGE_FLOATS (AS_FLOATS + BS_FLOATS)
#define GEMM_SMEM (GSTAGES * STAGE_FLOATS * 4)   // ~105 KB -> 2 CTA/SM

#define WDEG 64

// ---------------- scratch ----------------
__device__ float g_bufA[NN * DD];
__device__ float g_bufB[NN * DD];
__device__ float g_q[NN * DD];
__device__ float g_k[NN * DD];
__device__ float g_v[NN * DD];
__device__ float g_skip[NN * DD];
__device__ float g_Wt[LL * 4 * DD * DD];
__device__ float g_W5[LL * DD * 128];
__device__ float g_b5[LL * 128];
__device__ float g_WeT[LL * DD * EDIMF];
__device__ float g_ef[EE * EDIMF];
__device__ float g_efcsr[EE * EDIMF];
__device__ float g_alpha[EE * HH];
__device__ float g_P[NN * HH * EDIMF];
__device__ int   g_rowptr[NN + 1];
__device__ int   g_cnt[NN];
__device__ int   g_cur[NN];
__device__ int   g_srcidx[EE];

// ---------------- helpers ----------------
__device__ __forceinline__ void cp16(uint32_t dst, const float* src) {
    asm volatile("cp.async.cg.shared.global [%0], [%1], 16;" ::"r"(dst),
                 "l"(__cvta_generic_to_global(src)));
}
__device__ __forceinline__ void cp_commit() { asm volatile("cp.async.commit_group;"); }
__device__ __forceinline__ void cp_wait1() { asm volatile("cp.async.wait_group 1;"); }

__device__ __forceinline__ uint32_t f2tf32(float f) {
    uint32_t u;
    asm("cvt.rna.tf32.f32 %0, %1;" : "=r"(u) : "f"(f));
    return u;
}
__device__ __forceinline__ float round_tf32(float f) { return __uint_as_float(f2tf32(f)); }

__device__ __forceinline__ void mma_tf32(float* c, const uint32_t* a, const uint32_t* b) {
    asm volatile(
        "mma.sync.aligned.m16n8k8.row.col.f32.tf32.tf32.f32 "
        "{%0,%1,%2,%3}, {%4,%5,%6,%7}, {%8,%9}, {%0,%1,%2,%3};"
        : "+f"(c[0]), "+f"(c[1]), "+f"(c[2]), "+f"(c[3])
        : "r"(a[0]), "r"(a[1]), "r"(a[2]), "r"(a[3]), "r"(b[0]), "r"(b[1]));
}

// ================= megaprep: round(W,x) + CSR count + WeT + ef in one launch =================
#define WELEMS (LL * 4 * DD * DD / 4)
#define XELEMS (NN * DD / 4)
#define NB_W  ((WELEMS + 255) / 256)
#define NB_X  ((XELEMS + 255) / 256)
#define NB_CNT ((EE + 255) / 256)
#define NB_WET ((LL * DD * EDIMF + 255) / 256)
#define NB_EF ((EE + 255) / 256)
#define NB_TOTAL (NB_W + NB_X + NB_CNT + NB_WET + NB_EF)

__global__ void __launch_bounds__(256) megaprep_kernel(
    const float* __restrict__ Wq, const float* __restrict__ Wk,
    const float* __restrict__ Wv, const float* __restrict__ Ws,
    const float* __restrict__ x, float* __restrict__ Wt, float* __restrict__ xr,
    const int* __restrict__ edge_index, int* __restrict__ cnt,
    const float* __restrict__ We, float* __restrict__ WeT,
    const float* __restrict__ edge_attr, const float* __restrict__ rel_emb,
    const float* __restrict__ W_edge, const float* __restrict__ b_edge,
    float* __restrict__ ef) {
    int b = blockIdx.x;
    int t = threadIdx.x;
    if (b < NB_W) {
        int idx = b * 256 + t;
        if (idx < WELEMS) {
            int z = idx / (DD * DD / 4);
            int rem = idx % (DD * DD / 4);
            int l = z >> 2, w = z & 3;
            const float* W = (w == 0 ? Wq : w == 1 ? Wk : w == 2 ? Wv : Ws) + (size_t)l * DD * DD;
            float4 val = ((const float4*)W)[rem];
            val.x = round_tf32(val.x); val.y = round_tf32(val.y);
            val.z = round_tf32(val.z); val.w = round_tf32(val.w);
            ((float4*)Wt)[idx] = val;
        }
        return;
    }
    b -= NB_W;
    if (b < NB_X) {
        int idx = b * 256 + t;
        if (idx < XELEMS) {
            float4 val = ((const float4*)x)[idx];
            val.x = round_tf32(val.x); val.y = round_tf32(val.y);
            val.z = round_tf32(val.z); val.w = round_tf32(val.w);
            ((float4*)xr)[idx] = val;
        }
        return;
    }
    b -= NB_X;
    if (b < NB_CNT) {
        int e = b * 256 + t;
        if (e < EE) atomicAdd(&cnt[edge_index[EE + e]], 1);
        return;
    }
    b -= NB_CNT;
    if (b < NB_WET) {
        int idx = b * 256 + t;
        if (idx < LL * DD * EDIMF) {
            int l = idx / (DD * EDIMF);
            int rem = idx % (DD * EDIMF);
            int d = rem >> 4, i = rem & 15;
            WeT[idx] = We[(size_t)l * EDIMF * DD + (size_t)i * DD + d];
        }
        return;
    }
    b -= NB_WET;
    {
        __shared__ float sW[EDIMF * EDIMF];
        __shared__ float sB[EDIMF];
        __shared__ float sR[NRELC * (EDIMF - 1)];
        if (t < EDIMF * EDIMF) sW[t] = W_edge[t];
        if (t < EDIMF) sB[t] = b_edge[t];
        if (t < NRELC * (EDIMF - 1)) sR[t] = rel_emb[t];
        __syncthreads();
        int e = b * 256 + t;
        if (e >= EE) return;
        int r = (int)edge_attr[2 * e];
        r = min(max(r, 0), NRELC - 1);
        float feat[EDIMF];
#pragma unroll
        for (int i = 0; i < EDIMF - 1; i++) feat[i] = sR[r * (EDIMF - 1) + i];
        feat[EDIMF - 1] = edge_attr[2 * e + 1];
#pragma unroll
        for (int j = 0; j < EDIMF; j++) {
            float s = sB[j];
#pragma unroll
            for (int i = 0; i < EDIMF; i++) s += feat[i] * sW[i * EDIMF + j];
            ef[(size_t)e * EDIMF + j] = s;
        }
    }
}

// ================= scan (block 0) + compose (blocks 1..36), 1024 threads =================
__global__ void __launch_bounds__(1024) scan_compose_kernel(
    const int* __restrict__ cnt, int* __restrict__ rowptr,
    const float* __restrict__ Wq, const float* __restrict__ bq,
    const float* __restrict__ WeT, float* __restrict__ W5, float* __restrict__ b5) {
    int t = threadIdx.x;
    if (blockIdx.x == 0) {
        __shared__ int s[1024];
        int carry = 0;
        if (t == 0) rowptr[0] = 0;
        for (int base = 0; base < NN; base += 1024) {
            int i = base + t;
            s[t] = (i < NN) ? cnt[i] : 0;
            __syncthreads();
            for (int off = 1; off < 1024; off <<= 1) {
                int add = (t >= off) ? s[t - off] : 0;
                __syncthreads();
                s[t] += add;
                __syncthreads();
            }
            if (i < NN) rowptr[i + 1] = carry + s[t];
            int tot = s[1023];
            __syncthreads();
            carry += tot;
        }
        return;
    }
    int cb = blockIdx.x - 1;            // 0..35
    int l = cb / 12;
    int k0 = (cb % 12) * 64;
    int j = t & 63, kl = t >> 6;        // kl 0..15
    int h = j >> 4, i = j & 15;
    const float* wq_base = Wq + (size_t)l * DD * DD + h * CC;
    const float* wet = WeT + (size_t)l * DD * EDIMF + (size_t)(h * CC) * 16 + i;
    float* W5l = W5 + (size_t)l * DD * 128;
    for (int kk = kl; kk < 64; kk += 16) {
        int k = k0 + kk;
        const float* wq = wq_base + (size_t)k * DD;
        float s0 = 0.f, s1 = 0.f, s2 = 0.f, s3 = 0.f;
#pragma unroll 4
        for (int c = 0; c < CC; c += 4) {
            s0 = fmaf(wq[c + 0], wet[(c + 0) * 16], s0);
            s1 = fmaf(wq[c + 1], wet[(c + 1) * 16], s1);
            s2 = fmaf(wq[c + 2], wet[(c + 2) * 16], s2);
            s3 = fmaf(wq[c + 3], wet[(c + 3) * 16], s3);
        }
        W5l[(size_t)k * 128 + j] = round_tf32((s0 + s1) + (s2 + s3));
        W5l[(size_t)k * 128 + 64 + j] = 0.f;
    }
    if (k0 == 0 && kl == 0) {
        const float* bb = bq + (size_t)l * DD + h * CC;
        float s = 0.f;
#pragma unroll 4
        for (int c = 0; c < CC; c++) s = fmaf(bb[c], wet[c * 16], s);
        b5[l * 128 + j] = s;
        b5[l * 128 + 64 + j] = 0.f;
    }
}

// ================= fused Q/K/V/Skip/P GEMM; bx==25 blocks do the CSR scatter (L0 only) =================
__global__ void __launch_bounds__(256, 2) gemm5_kernel(
    const float* __restrict__ A, const float* __restrict__ Wt,
    const float* __restrict__ W5, const float* __restrict__ b5,
    const float* __restrict__ b0, const float* __restrict__ b1,
    const float* __restrict__ b2, const float* __restrict__ b3,
    float* __restrict__ o0, float* __restrict__ o1,
    float* __restrict__ o2, float* __restrict__ o3,
    float* __restrict__ oP,
    int do_scatter, const int* __restrict__ edge_index, const int* __restrict__ rowptr,
    int* __restrict__ cur, int* __restrict__ srcs,
    const float* __restrict__ ef, float* __restrict__ efc) {
    extern __shared__ float sm[];
    const int t = threadIdx.x;
    if (blockIdx.x == 25) {
        if (do_scatter) {
            for (int e = blockIdx.y * 256 + t; e < EE; e += 79 * 256) {
                int dst = edge_index[EE + e];
                int pos = rowptr[dst] + atomicAdd(&cur[dst], 1);
                srcs[pos] = edge_index[e];
                const float4* s = (const float4*)(ef + (size_t)e * EDIMF);
                float4* d = (float4*)(efc + (size_t)pos * EDIMF);
                d[0] = s[0]; d[1] = s[1]; d[2] = s[2]; d[3] = s[3];
            }
        }
        return;
    }
    const int warp = t >> 5, lane = t & 31;
    const int g = lane >> 2, qd = lane & 3;
    const int w = blockIdx.x / 6;           // 0..4
    const int n0 = (w < 4) ? (blockIdx.x % 6) * BN : 0;
    const int m0 = blockIdx.y * BM;
    const int wm = warp & 1, wn = warp >> 1;

    const float* W;
    const float* bias;
    float* out;
    int ldw, ostride;
    if (w < 4) {
        W = Wt + (size_t)w * DD * DD;
        bias = (w == 0 ? b0 : w == 1 ? b1 : w == 2 ? b2 : b3);
        out = (w == 0 ? o0 : w == 1 ? o1 : w == 2 ? o2 : o3);
        ldw = DD; ostride = DD;
    } else {
        W = W5; bias = b5; out = oP;
        ldw = 128; ostride = 64;
    }

    uint32_t smb = (uint32_t)__cvta_generic_to_shared(sm);

    float c[4][4][4];
#pragma unroll
    for (int mi = 0; mi < 4; mi++)
#pragma unroll
        for (int ni = 0; ni < 4; ni++)
#pragma unroll
            for (int r = 0; r < 4; r++) c[mi][ni][r] = 0.f;

    auto load_stage = [&](int slot, int kt) {
        int k0 = kt * BK;
        uint32_t AsB = smb + (uint32_t)(slot * STAGE_FLOATS) * 4u;
        uint32_t BsB = AsB + AS_FLOATS * 4u;
#pragma unroll
        for (int s = 0; s < 4; s++) {
            int i = t + s * 256;
            int row = i >> 3, c4 = (i & 7) * 4;
            int grow = m0 + row;
            const float* src = A + (size_t)(grow < NN ? grow : 0) * DD + k0 + c4;
            cp16(AsB + (uint32_t)(row * SA + c4) * 4u, src);
        }
#pragma unroll
        for (int s = 0; s < 4; s++) {
            int i = t + s * 256;
            int row = i >> 5, c4 = (i & 31) * 4;
            const float* src = W + (size_t)(k0 + row) * ldw + n0 + c4;
            cp16(BsB + (uint32_t)(row * SB + c4) * 4u, src);
        }
    };

    load_stage(0, 0);
    cp_commit();
    load_stage(1, 1);
    cp_commit();

    for (int kt = 0; kt < NKT; kt++) {
        cp_wait1();
        __syncthreads();
        int cn = kt + 2;
        if (cn < NKT) load_stage(cn % GSTAGES, cn);
        cp_commit();
        const uint32_t* As = (const uint32_t*)(sm + (kt % GSTAGES) * STAGE_FLOATS);
        const uint32_t* Bs = As + AS_FLOATS;
#pragma unroll
        for (int ks = 0; ks < 4; ks++) {
            int k0s = ks * 8;
            uint32_t a[4][4], b[4][2];
#pragma unroll
            for (int mi = 0; mi < 4; mi++) {
                int mrow = wm * 64 + mi * 16 + g;
                const uint32_t* p = As + mrow * SA + k0s + qd;
                a[mi][0] = p[0];
                a[mi][1] = p[8 * SA];
                a[mi][2] = p[4];
                a[mi][3] = p[8 * SA + 4];
            }
#pragma unroll
            for (int ni = 0; ni < 4; ni++) {
                int ncol = wn * 32 + ni * 8 + g;
                const uint32_t* p = Bs + (k0s + qd) * SB + ncol;
                b[ni][0] = p[0];
                b[ni][1] = p[4 * SB];
            }
#pragma unroll
            for (int mi = 0; mi < 4; mi++)
#pragma unroll
                for (int ni = 0; ni < 4; ni++) mma_tf32(c[mi][ni], a[mi], b[ni]);
        }
    }

#pragma unroll
    for (int mi = 0; mi < 4; mi++) {
#pragma unroll
        for (int rh = 0; rh < 2; rh++) {
            int grow = m0 + wm * 64 + mi * 16 + rh * 8 + g;
            if (grow >= NN) continue;
            float* orow = out + (size_t)grow * ostride + n0;
#pragma unroll
            for (int ni = 0; ni < 4; ni++) {
                int col = wn * 32 + ni * 8 + 2 * qd;
                if (w == 4 && col >= 64) continue;
                float2 val;
                val.x = c[mi][ni][rh * 2 + 0] + bias[n0 + col];
                val.y = c[mi][ni][rh * 2 + 1] + bias[n0 + col + 1];
                *(float2*)(orow + col) = val;
            }
        }
    }
}

// ================= fused attention: ONE WARP PER CTA (load-balanced) =================
__global__ void __launch_bounds__(32) node_fused_kernel(
    const float* __restrict__ q, const float* __restrict__ kk, const float* __restrict__ v,
    const float* __restrict__ skip, const float* __restrict__ efc, const float* __restrict__ P,
    const int* __restrict__ rowptr, const int* __restrict__ srcs,
    const float* __restrict__ We, float* __restrict__ galpha,
    float* __restrict__ out, int gelu) {
    __shared__ float abuf[WDEG * HH];
    __shared__ float Ssm[2 * 32];
    const int lane = threadIdx.x;
    const int n = blockIdx.x;
    const int start = rowptr[n], end = rowptr[n + 1];
    const int deg = end - start;
    const unsigned FULL = 0xffffffffu;
    const int h = lane >> 3, lg = lane & 7;

    float* wp = (deg <= WDEG) ? abuf : (galpha + (size_t)start * HH);

    const float4* qr = (const float4*)(q + (size_t)n * DD + h * CC);
    float4 qv[6];
#pragma unroll
    for (int j = 0; j < 6; j++) qv[j] = qr[lg + 8 * j];
    const float p0 = P[(size_t)n * (HH * EDIMF) + h * EDIMF + lg];
    const float p1 = P[(size_t)n * (HH * EDIMF) + h * EDIMF + lg + 8];

    for (int base = 0; base < deg; base += 32) {
        int cnt = min(32, deg - base);
        int srcReg = (base + lane < deg) ? srcs[start + base + lane] : 0;
        for (int i = 0; i < cnt; i++) {
            int src = __shfl_sync(FULL, srcReg, i);
            int e = start + base + i;
            const float4* kr = (const float4*)(kk + (size_t)src * DD + h * CC);
            float s = 0.f;
#pragma unroll
            for (int j = 0; j < 6; j++) {
                float4 kv = kr[lg + 8 * j];
                s = fmaf(qv[j].x, kv.x, s);
                s = fmaf(qv[j].y, kv.y, s);
                s = fmaf(qv[j].z, kv.z, s);
                s = fmaf(qv[j].w, kv.w, s);
            }
            s = fmaf(efc[(size_t)e * EDIMF + lg], p0, s);
            s = fmaf(efc[(size_t)e * EDIMF + lg + 8], p1, s);
            s += __shfl_xor_sync(FULL, s, 1);
            s += __shfl_xor_sync(FULL, s, 2);
            s += __shfl_xor_sync(FULL, s, 4);
            if (lg == 0) wp[(base + i) * HH + h] = s * 0.07216878364870322f;
        }
    }
    __syncwarp();

    if (lane < HH) {
        float m = -1e30f;
        for (int i = 0; i < deg; i++) m = fmaxf(m, wp[i * HH + lane]);
        float ssum = 0.f;
        for (int i = 0; i < deg; i++) {
            float wv = expf(wp[i * HH + lane] - m);
            wp[i * HH + lane] = wv;
            ssum += wv;
        }
        float inv = 1.f / (ssum + 1e-16f);
        for (int i = 0; i < deg; i++) wp[i * HH + lane] *= inv;
    }
    __syncwarp();

    float acc[24];
#pragma unroll
    for (int j = 0; j < 24; j++) acc[j] = 0.f;
    float sa = 0.f, sb = 0.f;
    const int iA = lane & 15;
    const int hA = lane >> 4, hB = 2 + (lane >> 4);
    for (int base = 0; base < deg; base += 32) {
        int cnt = min(32, deg - base);
        int srcReg = (base + lane < deg) ? srcs[start + base + lane] : 0;
        for (int i = 0; i < cnt; i++) {
            int src = __shfl_sync(FULL, srcReg, i);
            int idx = base + i;
            const float* vr = v + (size_t)src * DD;
            float w0 = wp[idx * HH + 0];
            float w1 = wp[idx * HH + 1];
            float w2 = wp[idx * HH + 2];
            float w3 = wp[idx * HH + 3];
#pragma unroll
            for (int j = 0; j < 24; j++) {
                float wj = (j < 6) ? w0 : (j < 12) ? w1 : (j < 18) ? w2 : w3;
                acc[j] = fmaf(wj, vr[lane + 32 * j], acc[j]);
            }
            float efA = efc[(size_t)(start + idx) * EDIMF + iA];
            sa = fmaf(wp[idx * HH + hA], efA, sa);
            sb = fmaf(wp[idx * HH + hB], efA, sb);
        }
    }
    Ssm[lane] = sa;
    Ssm[lane + 32] = sb;
    __syncwarp();

    const float* sk = skip + (size_t)n * DD;
    float* orow = out + (size_t)n * DD;
#pragma unroll
    for (int j = 0; j < 24; j++) {
        int c = lane + 32 * j;
        int hh = j / 6;
        float val = acc[j];
#pragma unroll
        for (int i = 0; i < 16; i++)
            val = fmaf(Ssm[hh * 16 + i], We[(size_t)i * DD + c], val);
        val += sk[c];
        if (gelu) {
            val = 0.5f * val * (1.f + erff(val * 0.7071067811865475f));
            val = round_tf32(val);
        }
        orow[c] = val;
    }
}

// ================= layernorm + global mean pool =================
__global__ void ln_pool_kernel(const float* __restrict__ h, float* __restrict__ out) {
    __shared__ float red[256];
    int t = threadIdx.x;
    float acc0 = 0.f, acc1 = 0.f, acc2 = 0.f;
    for (int n = blockIdx.x; n < NN; n += gridDim.x) {
        const float* row = h + (size_t)n * DD;
        float v0 = row[t], v1 = row[t + 256], v2 = row[t + 512];
        red[t] = v0 + v1 + v2;
        __syncthreads();
        for (int off = 128; off > 0; off >>= 1) {
            if (t < off) red[t] += red[t + off];
            __syncthreads();
        }
        float mu = red[0] * (1.f / DD);
        __syncthreads();
        float d0 = v0 - mu, d1 = v1 - mu, d2 = v2 - mu;
        red[t] = d0 * d0 + d1 * d1 + d2 * d2;
        __syncthreads();
        for (int off = 128; off > 0; off >>= 1) {
            if (t < off) red[t] += red[t + off];
            __syncthreads();
        }
        float rstd = rsqrtf(red[0] * (1.f / DD) + 1e-5f);
        __syncthreads();
        acc0 += d0 * rstd;
        acc1 += d1 * rstd;
        acc2 += d2 * rstd;
    }
    atomicAdd(&out[t], acc0);
    atomicAdd(&out[t + 256], acc1);
    atomicAdd(&out[t + 512], acc2);
}

__global__ void ln_final_kernel(float* __restrict__ out, const float* __restrict__ g,
                                const float* __restrict__ b) {
    int c = threadIdx.x + blockIdx.x * blockDim.x;
    if (c < DD) out[c] = out[c] * g[c] * (1.f / NN) + b[c];
}

// ================= launch =================
extern "C" void kernel_launch(void* const* d_in, const int* in_sizes, int n_in,
                              void* d_out, int out_size) {
    const float* x          = (const float*)d_in[0];
    const float* edge_attr  = (const float*)d_in[1];
    const int*   edge_index = (const int*)d_in[2];
    const float* rel_emb    = (const float*)d_in[3];
    const float* W_edge     = (const float*)d_in[4];
    const float* b_edge     = (const float*)d_in[5];
    const float* Wk         = (const float*)d_in[6];
    const float* bk         = (const float*)d_in[7];
    const float* Wq         = (const float*)d_in[8];
    const float* bq         = (const float*)d_in[9];
    const float* Wv         = (const float*)d_in[10];
    const float* bv         = (const float*)d_in[11];
    const float* We         = (const float*)d_in[12];
    const float* Wskip      = (const float*)d_in[13];
    const float* bskip      = (const float*)d_in[14];
    const float* ln_g       = (const float*)d_in[15];
    const float* ln_b       = (const float*)d_in[16];
    float* out = (float*)d_out;

    float *bufA, *bufB, *q, *k, *v, *skip, *ef, *efc, *alpha, *P, *Wt, *W5, *b5, *WeT;
    int *rowptr, *cnt, *cur, *srcidx;
    cudaGetSymbolAddress((void**)&bufA, g_bufA);
    cudaGetSymbolAddress((void**)&bufB, g_bufB);
    cudaGetSymbolAddress((void**)&q, g_q);
    cudaGetSymbolAddress((void**)&k, g_k);
    cudaGetSymbolAddress((void**)&v, g_v);
    cudaGetSymbolAddress((void**)&skip, g_skip);
    cudaGetSymbolAddress((void**)&ef, g_ef);
    cudaGetSymbolAddress((void**)&efc, g_efcsr);
    cudaGetSymbolAddress((void**)&alpha, g_alpha);
    cudaGetSymbolAddress((void**)&P, g_P);
    cudaGetSymbolAddress((void**)&Wt, g_Wt);
    cudaGetSymbolAddress((void**)&W5, g_W5);
    cudaGetSymbolAddress((void**)&b5, g_b5);
    cudaGetSymbolAddress((void**)&WeT, g_WeT);
    cudaGetSymbolAddress((void**)&rowptr, g_rowptr);
    cudaGetSymbolAddress((void**)&cnt, g_cnt);
    cudaGetSymbolAddress((void**)&cur, g_cur);
    cudaGetSymbolAddress((void**)&srcidx, g_srcidx);

    cudaFuncSetAttribute(gemm5_kernel, cudaFuncAttributeMaxDynamicSharedMemorySize, GEMM_SMEM);

    cudaMemsetAsync(cnt, 0, NN * sizeof(int));
    cudaMemsetAsync(cur, 0, NN * sizeof(int));
    // #1 megaprep, #2 scan+compose, #3 gemm5(L0, +scatter), #4 node_fused(L0) <- ncu slot
    megaprep_kernel<<<NB_TOTAL, 256>>>(Wq, Wk, Wv, Wskip, x, Wt, bufB,
                                       edge_index, cnt, We, WeT,
                                       edge_attr, rel_emb, W_edge, b_edge, ef);
    scan_compose_kernel<<<1 + LL * 12, 1024>>>(cnt, rowptr, Wq, bq, WeT, W5, b5);

    const float* hin = bufB;   // tf32-rounded x
    for (int l = 0; l < LL; l++) {
        const float* We_l = We + (size_t)l * EDIMF * DD;
        gemm5_kernel<<<dim3(26, (NN + BM - 1) / BM), 256, GEMM_SMEM>>>(
            hin, Wt + (size_t)l * 4 * DD * DD,
            W5 + (size_t)l * DD * 128, b5 + (size_t)l * 128,
            bq + (size_t)l * DD, bk + (size_t)l * DD, bv + (size_t)l * DD, bskip + (size_t)l * DD,
            q, k, v, skip, P,
            (l == 0) ? 1 : 0, edge_index, rowptr, cur, srcidx, ef, efc);
        float* hout = (l & 1) ? bufB : bufA;
        node_fused_kernel<<<NN, 32>>>(q, k, v, skip, efc, P, rowptr, srcidx, We_l,
                                      alpha, hout, (l < LL - 1) ? 1 : 0);
        hin = hout;
    }

    cudaMemsetAsync(out, 0, DD * sizeof(float));
    ln_pool_kernel<<<1024, 256>>>(hin, out);
    ln_final_kernel<<<3, 256>>>(out, ln_g, ln_b);
}